// round 4
// baseline (speedup 1.0000x reference)
#include <cuda_runtime.h>

#define Nn   10000
#define Ee   80000
#define ET   90000      // Ee + Nn self loops
#define FIN  128
#define D1   2048       // H1*C1
#define NH1  8
#define C1n  256
#define D2   32
#define NEG  0.2f

// ---------------- scratch (device globals; no allocations allowed) ----------
__device__ int   g_deg[Nn];
__device__ int   g_off[Nn + 1];
__device__ int   g_fill[Nn];
__device__ float g_selfattr[Nn * FIN];
__device__ int   g_csr_src[ET];
__device__ int   g_csr_eid[ET];
__device__ float g_xl1[Nn * D1];
__device__ float g_xr1[Nn * D1];
__device__ float g_h1 [Nn * D1];
__device__ float g_logits[ET * NH1];
__device__ float g_xl2[Nn * D2];
__device__ float g_xr2[Nn * D2];
__device__ float g_logits2[ET];

// ---------------- small setup kernels --------------------------------------
__global__ void k_init()
{
    int i = blockIdx.x * blockDim.x + threadIdx.x;
    if (i < Nn) { g_deg[i] = 0; g_fill[i] = 0; }
}

__global__ void k_count(const int* __restrict__ dstA)
{
    int i = blockIdx.x * blockDim.x + threadIdx.x;
    if (i < Ee) atomicAdd(&g_deg[dstA[i]], 1);
}

// exclusive scan of (deg[i]+1) -> g_off ; single block, Hillis-Steele chunks
__global__ __launch_bounds__(1024) void k_scan()
{
    __shared__ int sh[1024];
    __shared__ int carry;
    int tid = threadIdx.x;
    if (tid == 0) carry = 0;
    __syncthreads();
    for (int base = 0; base < Nn; base += 1024) {
        int i = base + tid;
        int v = (i < Nn) ? (g_deg[i] + 1) : 0;
        sh[tid] = v;
        __syncthreads();
        for (int off = 1; off < 1024; off <<= 1) {
            int t = (tid >= off) ? sh[tid - off] : 0;
            __syncthreads();
            sh[tid] += t;
            __syncthreads();
        }
        if (i < Nn) g_off[i] = carry + sh[tid] - v;   // exclusive
        __syncthreads();
        if (tid == 0) carry += sh[1023];
        __syncthreads();
    }
    if (tid == 0) g_off[Nn] = carry;   // == ET
}

__global__ void k_fill(const int* __restrict__ srcA, const int* __restrict__ dstA)
{
    int i = blockIdx.x * blockDim.x + threadIdx.x;
    if (i < Ee) {
        int d = dstA[i];
        int pos = g_off[d] + atomicAdd(&g_fill[d], 1);
        g_csr_src[pos] = srcA[i];
        g_csr_eid[pos] = i;
    } else if (i < Ee + Nn) {
        int n = i - Ee;                       // self loop goes in the reserved last slot
        int pos = g_off[n] + g_deg[n];
        g_csr_src[pos] = n;
        g_csr_eid[pos] = Ee + n;
    }
}

// self-loop edge_attr = mean of incoming edge attrs (fill_value='mean')
__global__ __launch_bounds__(128) void k_selfattr(const float* __restrict__ EA)
{
    int n = blockIdx.x;
    int c = threadIdx.x;
    int beg = g_off[n], dg = g_deg[n];
    float s = 0.f;
    for (int j = 0; j < dg; j++)
        s += EA[g_csr_eid[beg + j] * FIN + c];
    g_selfattr[n * FIN + c] = s / fmaxf((float)dg, 1.0f);
}

// ---------------- GEMM1: xl1 / xr1 = x @ W + b  ([10000,128]x[128,2048]) ----
__global__ __launch_bounds__(256) void k_gemm1(
    const float* __restrict__ A, const float* __restrict__ B,
    const float* __restrict__ bias, int which)
{
    __shared__ float sA[64 * 65];
    __shared__ __align__(16) float sB[64 * 64];
    int tid = threadIdx.x;
    int c0 = blockIdx.x * 64;
    int r0 = blockIdx.y * 64;
    int ty = tid >> 4, tx = tid & 15;

    float acc[4][4];
#pragma unroll
    for (int i = 0; i < 4; i++)
#pragma unroll
        for (int j = 0; j < 4; j++) acc[i][j] = 0.f;

    for (int kc = 0; kc < FIN; kc += 64) {
        for (int i = tid; i < 1024; i += 256) {
            int row = i >> 4;
            int c = (i & 15) << 2;
            float4 v = make_float4(0.f, 0.f, 0.f, 0.f);
            if (r0 + row < Nn) v = *(const float4*)&A[(r0 + row) * FIN + kc + c];
            float* dp = sA + row * 65 + c;
            dp[0] = v.x; dp[1] = v.y; dp[2] = v.z; dp[3] = v.w;
        }
        for (int i = tid; i < 1024; i += 256) {
            int k = i >> 4;
            int c = (i & 15) << 2;
            *(float4*)&sB[k * 64 + c] = *(const float4*)&B[(kc + k) * D1 + c0 + c];
        }
        __syncthreads();
#pragma unroll 8
        for (int k = 0; k < 64; k++) {
            float a0 = sA[(ty * 4 + 0) * 65 + k];
            float a1 = sA[(ty * 4 + 1) * 65 + k];
            float a2 = sA[(ty * 4 + 2) * 65 + k];
            float a3 = sA[(ty * 4 + 3) * 65 + k];
            float4 b = *(float4*)&sB[k * 64 + tx * 4];
            acc[0][0] += a0 * b.x; acc[0][1] += a0 * b.y; acc[0][2] += a0 * b.z; acc[0][3] += a0 * b.w;
            acc[1][0] += a1 * b.x; acc[1][1] += a1 * b.y; acc[1][2] += a1 * b.z; acc[1][3] += a1 * b.w;
            acc[2][0] += a2 * b.x; acc[2][1] += a2 * b.y; acc[2][2] += a2 * b.z; acc[2][3] += a2 * b.w;
            acc[3][0] += a3 * b.x; acc[3][1] += a3 * b.y; acc[3][2] += a3 * b.z; acc[3][3] += a3 * b.w;
        }
        __syncthreads();
    }
    float4 bi = *(const float4*)&bias[c0 + tx * 4];
    float* C = which ? g_xr1 : g_xl1;
#pragma unroll
    for (int i = 0; i < 4; i++) {
        int row = r0 + ty * 4 + i;
        if (row < Nn) {
            float4 o = make_float4(acc[i][0] + bi.x, acc[i][1] + bi.y,
                                   acc[i][2] + bi.z, acc[i][3] + bi.w);
            *(float4*)&C[row * D1 + c0 + tx * 4] = o;
        }
    }
}

// ---------------- fused edge projection + leaky-relu + attention logits -----
// per block: 128 edges, loops 32 col-tiles of 64; thread = 4 edges x 8 cols
__global__ __launch_bounds__(256) void k_elogits1(
    const float* __restrict__ EA, const float* __restrict__ We1,
    const float* __restrict__ att1,
    const int* __restrict__ srcA, const int* __restrict__ dstA)
{
    extern __shared__ float sm[];
    float* sEA  = sm;                       // 128*129
    float* sB   = sm + 128 * 129;           // 128*64
    float* sLog = sB + 128 * 64;            // 128*8
    int*   sSrc = (int*)(sLog + 128 * 8);   // 128
    int*   sDst = sSrc + 128;               // 128

    const int tid = threadIdx.x;
    const int eBase = blockIdx.x * 128;
    const int g = tid >> 3;
    const int cg8 = (tid & 7) << 3;

    for (int i = tid; i < 4096; i += 256) {
        int el = i >> 5;
        int c = (i & 31) << 2;
        int e = eBase + el;
        float4 v = make_float4(0.f, 0.f, 0.f, 0.f);
        if (e < ET) {
            const float* p = (e < Ee) ? (EA + e * FIN + c)
                                      : (g_selfattr + (e - Ee) * FIN + c);
            v = *(const float4*)p;
        }
        float* dp = sEA + el * 129 + c;
        dp[0] = v.x; dp[1] = v.y; dp[2] = v.z; dp[3] = v.w;
    }
    if (tid < 128) {
        int e = eBase + tid;
        int s = 0, d = 0;
        if (e < ET) {
            if (e < Ee) { s = srcA[e]; d = dstA[e]; }
            else        { s = e - Ee;  d = s; }
        }
        sSrc[tid] = s; sDst[tid] = d;
    }
    for (int i = tid; i < 1024; i += 256) sLog[i] = 0.f;
    __syncthreads();

    int eb[4];
#pragma unroll
    for (int i = 0; i < 4; i++) eb[i] = (g * 4 + i) * 129;

    for (int t = 0; t < 32; t++) {
        for (int i = tid; i < 2048; i += 256) {
            int k = i >> 4;
            int c = (i & 15) << 2;
            *(float4*)&sB[k * 64 + c] = *(const float4*)&We1[k * D1 + t * 64 + c];
        }
        __syncthreads();

        float acc[4][8];
#pragma unroll
        for (int i = 0; i < 4; i++)
#pragma unroll
            for (int j = 0; j < 8; j++) acc[i][j] = 0.f;

#pragma unroll 4
        for (int k = 0; k < 128; k++) {
            float4 b0 = *(float4*)&sB[k * 64 + cg8];
            float4 b1 = *(float4*)&sB[k * 64 + cg8 + 4];
            float bv[8] = { b0.x, b0.y, b0.z, b0.w, b1.x, b1.y, b1.z, b1.w };
#pragma unroll
            for (int i = 0; i < 4; i++) {
                float a = sEA[eb[i] + k];
#pragma unroll
                for (int j = 0; j < 8; j++) acc[i][j] += a * bv[j];
            }
        }

        int h = t >> 2;
        int cb = t * 64 + cg8;
        int cin = cb - h * C1n;
        float4 at0 = *(const float4*)&att1[h * C1n + cin];
        float4 at1 = *(const float4*)&att1[h * C1n + cin + 4];
        float av[8] = { at0.x, at0.y, at0.z, at0.w, at1.x, at1.y, at1.z, at1.w };

#pragma unroll
        for (int i = 0; i < 4; i++) {
            int el = g * 4 + i;
            int s = sSrc[el], d = sDst[el];
            float4 l0 = *(const float4*)&g_xl1[s * D1 + cb];
            float4 l1 = *(const float4*)&g_xl1[s * D1 + cb + 4];
            float4 q0 = *(const float4*)&g_xr1[d * D1 + cb];
            float4 q1 = *(const float4*)&g_xr1[d * D1 + cb + 4];
            float lv[8] = { l0.x + q0.x, l0.y + q0.y, l0.z + q0.z, l0.w + q0.w,
                            l1.x + q1.x, l1.y + q1.y, l1.z + q1.z, l1.w + q1.w };
            float p = 0.f;
#pragma unroll
            for (int j = 0; j < 8; j++) {
                float v = acc[i][j] + lv[j];
                v = v > 0.f ? v : NEG * v;
                p += v * av[j];
            }
            p += __shfl_xor_sync(0xffffffffu, p, 1);
            p += __shfl_xor_sync(0xffffffffu, p, 2);
            p += __shfl_xor_sync(0xffffffffu, p, 4);
            if (((tid & 7) == 0) && (eBase + el < ET)) sLog[el * 8 + h] += p;
        }
        __syncthreads();
    }

    for (int i = tid; i < 1024; i += 256) {
        int el = i >> 3, h = i & 7;
        int e = eBase + el;
        if (e < ET) g_logits[e * 8 + h] = sLog[i];
    }
}

// ---------------- layer-1 segment softmax + aggregation + ReLU --------------
__global__ __launch_bounds__(256) void k_agg1(const float* __restrict__ b1)
{
    int n = blockIdx.x;
    int tid = threadIdx.x;
    int beg = g_off[n];
    int cnt = g_deg[n] + 1;
    __shared__ float sm_m[NH1], sm_s[NH1];
    if (tid < NH1) {
        float m = -1e30f;
        for (int j = 0; j < cnt; j++)
            m = fmaxf(m, g_logits[g_csr_eid[beg + j] * 8 + tid]);
        float s = 0.f;
        for (int j = 0; j < cnt; j++)
            s += expf(g_logits[g_csr_eid[beg + j] * 8 + tid] - m);
        sm_m[tid] = m; sm_s[tid] = s;
    }
    __syncthreads();
    float mm[8], si[8];
#pragma unroll
    for (int h = 0; h < 8; h++) { mm[h] = sm_m[h]; si[h] = 1.f / sm_s[h]; }
    float r[8];
#pragma unroll
    for (int h = 0; h < 8; h++) r[h] = 0.f;
    for (int j = 0; j < cnt; j++) {
        int eid = g_csr_eid[beg + j];
        int s = g_csr_src[beg + j];
        const float* xrow = g_xl1 + s * D1;
#pragma unroll
        for (int h = 0; h < 8; h++) {
            float w = expf(g_logits[eid * 8 + h] - mm[h]) * si[h];
            r[h] += w * xrow[tid + 256 * h];
        }
    }
#pragma unroll
    for (int h = 0; h < 8; h++) {
        int c = tid + 256 * h;
        g_h1[n * D1 + c] = fmaxf(r[h] + b1[c], 0.f);
    }
}

// ---------------- GEMM2: xl2/xr2 = h1 @ {Wl2|Wr2} + bias  -------------------
__global__ __launch_bounds__(256) void k_gemm2(
    const float* __restrict__ Wl2, const float* __restrict__ bl2,
    const float* __restrict__ Wr2, const float* __restrict__ br2)
{
    __shared__ float sA[64 * 33];
    __shared__ __align__(16) float sB[32 * 64];
    int tid = threadIdx.x;
    int r0 = blockIdx.x * 64;
    int ty = tid >> 4, tx = tid & 15;

    float acc[4][4];
#pragma unroll
    for (int i = 0; i < 4; i++)
#pragma unroll
        for (int j = 0; j < 4; j++) acc[i][j] = 0.f;

    for (int kc = 0; kc < D1; kc += 32) {
        for (int i = tid; i < 512; i += 256) {
            int row = i >> 3;
            int c = (i & 7) << 2;
            float4 v = make_float4(0.f, 0.f, 0.f, 0.f);
            if (r0 + row < Nn) v = *(const float4*)&g_h1[(r0 + row) * D1 + kc + c];
            float* dp = sA + row * 33 + c;
            dp[0] = v.x; dp[1] = v.y; dp[2] = v.z; dp[3] = v.w;
        }
        for (int i = tid; i < 512; i += 256) {
            int kr = i >> 4;
            int c = (i & 15) << 2;
            float4 v;
            if (c < 32) v = *(const float4*)&Wl2[(kc + kr) * D2 + c];
            else        v = *(const float4*)&Wr2[(kc + kr) * D2 + (c - 32)];
            *(float4*)&sB[kr * 64 + c] = v;
        }
        __syncthreads();
#pragma unroll 8
        for (int k = 0; k < 32; k++) {
            float a0 = sA[(ty * 4 + 0) * 33 + k];
            float a1 = sA[(ty * 4 + 1) * 33 + k];
            float a2 = sA[(ty * 4 + 2) * 33 + k];
            float a3 = sA[(ty * 4 + 3) * 33 + k];
            float4 b = *(float4*)&sB[k * 64 + tx * 4];
            acc[0][0] += a0 * b.x; acc[0][1] += a0 * b.y; acc[0][2] += a0 * b.z; acc[0][3] += a0 * b.w;
            acc[1][0] += a1 * b.x; acc[1][1] += a1 * b.y; acc[1][2] += a1 * b.z; acc[1][3] += a1 * b.w;
            acc[2][0] += a2 * b.x; acc[2][1] += a2 * b.y; acc[2][2] += a2 * b.z; acc[2][3] += a2 * b.w;
            acc[3][0] += a3 * b.x; acc[3][1] += a3 * b.y; acc[3][2] += a3 * b.z; acc[3][3] += a3 * b.w;
        }
        __syncthreads();
    }
    int c = tx * 4;
    bool left = (c < 32);
    int cc = left ? c : c - 32;
    const float* bias = left ? bl2 : br2;
    float* Cout = left ? g_xl2 : g_xr2;
    float4 bi = *(const float4*)&bias[cc];
#pragma unroll
    for (int i = 0; i < 4; i++) {
        int row = r0 + ty * 4 + i;
        if (row < Nn) {
            float4 o = make_float4(acc[i][0] + bi.x, acc[i][1] + bi.y,
                                   acc[i][2] + bi.z, acc[i][3] + bi.w);
            *(float4*)&Cout[row * D2 + cc] = o;
        }
    }
}

// ---------------- layer-2 edge logits (warp per edge) -----------------------
__global__ __launch_bounds__(256) void k_elogits2(
    const float* __restrict__ EA, const float* __restrict__ We2,
    const float* __restrict__ att2,
    const int* __restrict__ srcA, const int* __restrict__ dstA)
{
    __shared__ float sW[FIN * D2];
    __shared__ float sAtt[D2];
    int tid = threadIdx.x;
    for (int i = tid; i < FIN * D2; i += 256) sW[i] = We2[i];
    if (tid < D2) sAtt[tid] = att2[tid];
    __syncthreads();

    int wid = tid >> 5, lane = tid & 31;
    int e = blockIdx.x * 8 + wid;
    bool valid = (e < ET);
    int s = 0, d = 0;
    float a0 = 0.f, a1 = 0.f, a2 = 0.f, a3 = 0.f;
    if (valid) {
        if (e < Ee) { s = srcA[e]; d = dstA[e]; }
        else        { s = e - Ee;  d = s; }
        const float* row = (e < Ee) ? (EA + e * FIN) : (g_selfattr + (e - Ee) * FIN);
        a0 = row[lane]; a1 = row[lane + 32]; a2 = row[lane + 64]; a3 = row[lane + 96];
    }
    float acc = 0.f;
#pragma unroll
    for (int kk = 0; kk < 32; kk++)
        acc += __shfl_sync(0xffffffffu, a0, kk) * sW[kk * D2 + lane];
#pragma unroll
    for (int kk = 0; kk < 32; kk++)
        acc += __shfl_sync(0xffffffffu, a1, kk) * sW[(32 + kk) * D2 + lane];
#pragma unroll
    for (int kk = 0; kk < 32; kk++)
        acc += __shfl_sync(0xffffffffu, a2, kk) * sW[(64 + kk) * D2 + lane];
#pragma unroll
    for (int kk = 0; kk < 32; kk++)
        acc += __shfl_sync(0xffffffffu, a3, kk) * sW[(96 + kk) * D2 + lane];

    float u = acc;
    if (valid) u += g_xl2[s * D2 + lane] + g_xr2[d * D2 + lane];
    u = u > 0.f ? u : NEG * u;
    float p = u * sAtt[lane];
    p += __shfl_xor_sync(0xffffffffu, p, 16);
    p += __shfl_xor_sync(0xffffffffu, p, 8);
    p += __shfl_xor_sync(0xffffffffu, p, 4);
    p += __shfl_xor_sync(0xffffffffu, p, 2);
    p += __shfl_xor_sync(0xffffffffu, p, 1);
    if (valid && lane == 0) g_logits2[e] = p;
}

// ---------------- layer-2 softmax + aggregation + ReLU (warp per node) ------
__global__ __launch_bounds__(256) void k_agg2(const float* __restrict__ b2,
                                              float* __restrict__ out)
{
    int gid = blockIdx.x * 256 + threadIdx.x;
    int n = gid >> 5;
    int lane = gid & 31;
    if (n >= Nn) return;
    int beg = g_off[n];
    int cnt = g_deg[n] + 1;
    float m = -1e30f;
    for (int j = 0; j < cnt; j++)
        m = fmaxf(m, g_logits2[g_csr_eid[beg + j]]);
    float sden = 0.f;
    for (int j = 0; j < cnt; j++)
        sden += expf(g_logits2[g_csr_eid[beg + j]] - m);
    float inv = 1.f / sden;
    float o = 0.f;
    for (int j = 0; j < cnt; j++) {
        int eid = g_csr_eid[beg + j];
        int sn = g_csr_src[beg + j];
        float w = expf(g_logits2[eid] - m) * inv;
        o += w * g_xl2[sn * D2 + lane];
    }
    out[n * D2 + lane] = fmaxf(o + b2[lane], 0.f);
}

// ---------------- launch -----------------------------------------------------
extern "C" void kernel_launch(void* const* d_in, const int* in_sizes, int n_in,
                              void* d_out, int out_size)
{
    const float* x    = (const float*)d_in[0];
    const int*   ei   = (const int*)  d_in[1];
    const float* ea   = (const float*)d_in[2];
    const float* Wl1  = (const float*)d_in[3];
    const float* bl1  = (const float*)d_in[4];
    const float* Wr1  = (const float*)d_in[5];
    const float* br1  = (const float*)d_in[6];
    const float* We1  = (const float*)d_in[7];
    const float* att1 = (const float*)d_in[8];
    const float* b1   = (const float*)d_in[9];
    const float* Wl2  = (const float*)d_in[10];
    const float* bl2  = (const float*)d_in[11];
    const float* Wr2  = (const float*)d_in[12];
    const float* br2  = (const float*)d_in[13];
    const float* We2  = (const float*)d_in[14];
    const float* att2 = (const float*)d_in[15];
    const float* b2   = (const float*)d_in[16];
    float* out = (float*)d_out;

    const int* srcA = ei;
    const int* dstA = ei + Ee;

    const size_t SM_EL1 = (size_t)(128 * 129 + 128 * 64 + 128 * 8) * sizeof(float)
                        + 256 * sizeof(int);
    cudaFuncSetAttribute(k_elogits1, cudaFuncAttributeMaxDynamicSharedMemorySize,
                         (int)SM_EL1);

    k_init <<<(Nn + 255) / 256, 256>>>();
    k_count<<<(Ee + 255) / 256, 256>>>(dstA);
    k_scan <<<1, 1024>>>();
    k_fill <<<(Ee + Nn + 255) / 256, 256>>>(srcA, dstA);
    k_selfattr<<<Nn, 128>>>(ea);

    dim3 g1(D1 / 64, (Nn + 63) / 64);
    k_gemm1<<<g1, 256>>>(x, Wl1, bl1, 0);
    k_gemm1<<<g1, 256>>>(x, Wr1, br1, 1);

    k_elogits1<<<(ET + 127) / 128, 256, SM_EL1>>>(ea, We1, att1, srcA, dstA);
    k_agg1<<<Nn, 256>>>(b1);

    k_gemm2<<<(Nn + 63) / 64, 256>>>(Wl2, bl2, Wr2, br2);
    k_elogits2<<<(ET + 7) / 8, 256>>>(ea, We2, att2, srcA, dstA);
    k_agg2<<<(Nn * 32 + 255) / 256, 256>>>(b2, out);

    (void)in_sizes; (void)n_in; (void)out_size;
}

// round 8
// speedup vs baseline: 1.0051x; 1.0051x over previous
#include <cuda_runtime.h>

#define Nn   10000
#define Ee   80000
#define ET   90000      // Ee + Nn self loops
#define FIN  128
#define D1   2048       // H1*C1
#define NH1  8
#define C1n  256
#define D2   32
#define NEG  0.2f

// packed fp32x2 FMA (sm_103a FFMA2 — only reachable via PTX)
#define FFMA2(d, a, b) \
    asm("fma.rn.f32x2 %0, %1, %2, %0;" : "+l"(d) : "l"(a), "l"(b))
#define PACK2(d, x) \
    asm("mov.b64 %0, {%1, %1};" : "=l"(d) : "f"(x))
#define UNPACK2(lo, hi, v) \
    asm("mov.b64 {%0, %1}, %2;" : "=f"(lo), "=f"(hi) : "l"(v))

typedef unsigned long long u64t;

// ---------------- scratch (device globals; no allocations allowed) ----------
__device__ int   g_deg[Nn];
__device__ int   g_off[Nn + 1];
__device__ int   g_fill[Nn];
__device__ float g_selfattr[Nn * FIN];
__device__ int   g_csr_src[ET];
__device__ int   g_csr_eid[ET];
__device__ float g_xl1[Nn * D1];
__device__ float g_xr1[Nn * D1];
__device__ float g_h1 [Nn * D1];
__device__ float g_logits[ET * NH1];
__device__ float g_xl2[Nn * D2];
__device__ float g_xr2[Nn * D2];
__device__ float g_logits2[ET];

// ---------------- small setup kernels --------------------------------------
__global__ void k_init()
{
    int i = blockIdx.x * blockDim.x + threadIdx.x;
    if (i < Nn) { g_deg[i] = 0; g_fill[i] = 0; }
}

__global__ void k_count(const int* __restrict__ dstA)
{
    int i = blockIdx.x * blockDim.x + threadIdx.x;
    if (i < Ee) atomicAdd(&g_deg[dstA[i]], 1);
}

// exclusive scan of (deg[i]+1) -> g_off ; single block, Hillis-Steele chunks
__global__ __launch_bounds__(1024) void k_scan()
{
    __shared__ int sh[1024];
    __shared__ int carry;
    int tid = threadIdx.x;
    if (tid == 0) carry = 0;
    __syncthreads();
    for (int base = 0; base < Nn; base += 1024) {
        int i = base + tid;
        int v = (i < Nn) ? (g_deg[i] + 1) : 0;
        sh[tid] = v;
        __syncthreads();
        for (int off = 1; off < 1024; off <<= 1) {
            int t = (tid >= off) ? sh[tid - off] : 0;
            __syncthreads();
            sh[tid] += t;
            __syncthreads();
        }
        if (i < Nn) g_off[i] = carry + sh[tid] - v;   // exclusive
        __syncthreads();
        if (tid == 0) carry += sh[1023];
        __syncthreads();
    }
    if (tid == 0) g_off[Nn] = carry;   // == ET
}

__global__ void k_fill(const int* __restrict__ srcA, const int* __restrict__ dstA)
{
    int i = blockIdx.x * blockDim.x + threadIdx.x;
    if (i < Ee) {
        int d = dstA[i];
        int pos = g_off[d] + atomicAdd(&g_fill[d], 1);
        g_csr_src[pos] = srcA[i];
        g_csr_eid[pos] = i;
    } else if (i < Ee + Nn) {
        int n = i - Ee;                       // self loop goes in the reserved last slot
        int pos = g_off[n] + g_deg[n];
        g_csr_src[pos] = n;
        g_csr_eid[pos] = Ee + n;
    }
}

// self-loop edge_attr = mean of incoming edge attrs (fill_value='mean')
__global__ __launch_bounds__(128) void k_selfattr(const float* __restrict__ EA)
{
    int n = blockIdx.x;
    int c = threadIdx.x;
    int beg = g_off[n], dg = g_deg[n];
    float s = 0.f;
    for (int j = 0; j < dg; j++)
        s += EA[g_csr_eid[beg + j] * FIN + c];
    g_selfattr[n * FIN + c] = s / fmaxf((float)dg, 1.0f);
}

// ---------------- GEMM1: xl1 / xr1 = x @ W + b  ([10000,128]x[128,2048]) ----
__global__ __launch_bounds__(256) void k_gemm1(
    const float* __restrict__ A, const float* __restrict__ B,
    const float* __restrict__ bias, int which)
{
    __shared__ float sA[64 * 65];
    __shared__ __align__(16) float sB[64 * 64];
    int tid = threadIdx.x;
    int c0 = blockIdx.x * 64;
    int r0 = blockIdx.y * 64;
    int ty = tid >> 4, tx = tid & 15;

    u64t acc2[4][2];
#pragma unroll
    for (int i = 0; i < 4; i++)
#pragma unroll
        for (int j = 0; j < 2; j++) acc2[i][j] = 0ull;

    for (int kc = 0; kc < FIN; kc += 64) {
        for (int i = tid; i < 1024; i += 256) {
            int row = i >> 4;
            int c = (i & 15) << 2;
            float4 v = make_float4(0.f, 0.f, 0.f, 0.f);
            if (r0 + row < Nn) v = *(const float4*)&A[(r0 + row) * FIN + kc + c];
            float* dp = sA + row * 65 + c;
            dp[0] = v.x; dp[1] = v.y; dp[2] = v.z; dp[3] = v.w;
        }
        for (int i = tid; i < 1024; i += 256) {
            int k = i >> 4;
            int c = (i & 15) << 2;
            *(float4*)&sB[k * 64 + c] = *(const float4*)&B[(kc + k) * D1 + c0 + c];
        }
        __syncthreads();
#pragma unroll 8
        for (int k = 0; k < 64; k++) {
            const u64t* bp = (const u64t*)&sB[k * 64 + tx * 4];
            u64t b0 = bp[0], b1 = bp[1];
#pragma unroll
            for (int i = 0; i < 4; i++) {
                float a = sA[(ty * 4 + i) * 65 + k];
                u64t a2; PACK2(a2, a);
                FFMA2(acc2[i][0], a2, b0);
                FFMA2(acc2[i][1], a2, b1);
            }
        }
        __syncthreads();
    }
    float4 bi = *(const float4*)&bias[c0 + tx * 4];
    float* C = which ? g_xr1 : g_xl1;
#pragma unroll
    for (int i = 0; i < 4; i++) {
        int row = r0 + ty * 4 + i;
        if (row < Nn) {
            float v0, v1, v2, v3;
            UNPACK2(v0, v1, acc2[i][0]);
            UNPACK2(v2, v3, acc2[i][1]);
            float4 o = make_float4(v0 + bi.x, v1 + bi.y, v2 + bi.z, v3 + bi.w);
            *(float4*)&C[row * D1 + c0 + tx * 4] = o;
        }
    }
}

// ---------------- fused edge projection + leaky-relu + attention logits -----
// per block: 128 edges, loops 32 col-tiles of 64; thread = 4 edges x 8 cols
__global__ __launch_bounds__(256) void k_elogits1(
    const float* __restrict__ EA, const float* __restrict__ We1,
    const float* __restrict__ att1,
    const int* __restrict__ srcA, const int* __restrict__ dstA)
{
    extern __shared__ float sm[];
    float* sEA  = sm;                       // 128*129
    float* sB   = sm + 128 * 129;           // 128*64
    float* sLog = sB + 128 * 64;            // 128*8
    int*   sSrc = (int*)(sLog + 128 * 8);   // 128
    int*   sDst = sSrc + 128;               // 128

    const int tid = threadIdx.x;
    const int eBase = blockIdx.x * 128;
    const int g = tid >> 3;
    const int cg8 = (tid & 7) << 3;

    for (int i = tid; i < 4096; i += 256) {
        int el = i >> 5;
        int c = (i & 31) << 2;
        int e = eBase + el;
        float4 v = make_float4(0.f, 0.f, 0.f, 0.f);
        if (e < ET) {
            const float* p = (e < Ee) ? (EA + e * FIN + c)
                                      : (g_selfattr + (e - Ee) * FIN + c);
            v = *(const float4*)p;
        }
        float* dp = sEA + el * 129 + c;
        dp[0] = v.x; dp[1] = v.y; dp[2] = v.z; dp[3] = v.w;
    }
    if (tid < 128) {
        int e = eBase + tid;
        int s = 0, d = 0;
        if (e < ET) {
            if (e < Ee) { s = srcA[e]; d = dstA[e]; }
            else        { s = e - Ee;  d = s; }
        }
        sSrc[tid] = s; sDst[tid] = d;
    }
    for (int i = tid; i < 1024; i += 256) sLog[i] = 0.f;
    __syncthreads();

    int eb[4];
#pragma unroll
    for (int i = 0; i < 4; i++) eb[i] = (g * 4 + i) * 129;

    for (int t = 0; t < 32; t++) {
        for (int i = tid; i < 2048; i += 256) {
            int k = i >> 4;
            int c = (i & 15) << 2;
            *(float4*)&sB[k * 64 + c] = *(const float4*)&We1[k * D1 + t * 64 + c];
        }
        __syncthreads();

        u64t acc2[4][4];
#pragma unroll
        for (int i = 0; i < 4; i++)
#pragma unroll
            for (int j = 0; j < 4; j++) acc2[i][j] = 0ull;

#pragma unroll 4
        for (int k = 0; k < 128; k++) {
            const u64t* bp = (const u64t*)&sB[k * 64 + cg8];
            u64t b0 = bp[0], b1 = bp[1], b2 = bp[2], b3 = bp[3];
#pragma unroll
            for (int i = 0; i < 4; i++) {
                float a = sEA[eb[i] + k];
                u64t a2; PACK2(a2, a);
                FFMA2(acc2[i][0], a2, b0);
                FFMA2(acc2[i][1], a2, b1);
                FFMA2(acc2[i][2], a2, b2);
                FFMA2(acc2[i][3], a2, b3);
            }
        }

        int h = t >> 2;
        int cb = t * 64 + cg8;
        int cin = cb - h * C1n;
        float4 at0 = *(const float4*)&att1[h * C1n + cin];
        float4 at1 = *(const float4*)&att1[h * C1n + cin + 4];
        float av[8] = { at0.x, at0.y, at0.z, at0.w, at1.x, at1.y, at1.z, at1.w };

#pragma unroll
        for (int i = 0; i < 4; i++) {
            int el = g * 4 + i;
            int s = sSrc[el], d = sDst[el];
            float4 l0 = *(const float4*)&g_xl1[s * D1 + cb];
            float4 l1 = *(const float4*)&g_xl1[s * D1 + cb + 4];
            float4 q0 = *(const float4*)&g_xr1[d * D1 + cb];
            float4 q1 = *(const float4*)&g_xr1[d * D1 + cb + 4];
            float lv[8] = { l0.x + q0.x, l0.y + q0.y, l0.z + q0.z, l0.w + q0.w,
                            l1.x + q1.x, l1.y + q1.y, l1.z + q1.z, l1.w + q1.w };
            float ac[8];
            UNPACK2(ac[0], ac[1], acc2[i][0]);
            UNPACK2(ac[2], ac[3], acc2[i][1]);
            UNPACK2(ac[4], ac[5], acc2[i][2]);
            UNPACK2(ac[6], ac[7], acc2[i][3]);
            float p = 0.f;
#pragma unroll
            for (int j = 0; j < 8; j++) {
                float v = ac[j] + lv[j];
                v = v > 0.f ? v : NEG * v;
                p += v * av[j];
            }
            p += __shfl_xor_sync(0xffffffffu, p, 1);
            p += __shfl_xor_sync(0xffffffffu, p, 2);
            p += __shfl_xor_sync(0xffffffffu, p, 4);
            if (((tid & 7) == 0) && (eBase + el < ET)) sLog[el * 8 + h] += p;
        }
        __syncthreads();
    }

    for (int i = tid; i < 1024; i += 256) {
        int el = i >> 3, h = i & 7;
        int e = eBase + el;
        if (e < ET) g_logits[e * 8 + h] = sLog[i];
    }
}

// ---------------- layer-1 segment softmax + aggregation + ReLU --------------
__global__ __launch_bounds__(256) void k_agg1(const float* __restrict__ b1)
{
    int n = blockIdx.x;
    int tid = threadIdx.x;
    int beg = g_off[n];
    int cnt = g_deg[n] + 1;
    __shared__ float sm_m[NH1], sm_s[NH1];
    if (tid < NH1) {
        float m = -1e30f;
        for (int j = 0; j < cnt; j++)
            m = fmaxf(m, g_logits[g_csr_eid[beg + j] * 8 + tid]);
        float s = 0.f;
        for (int j = 0; j < cnt; j++)
            s += expf(g_logits[g_csr_eid[beg + j] * 8 + tid] - m);
        sm_m[tid] = m; sm_s[tid] = s;
    }
    __syncthreads();
    float mm[8], si[8];
#pragma unroll
    for (int h = 0; h < 8; h++) { mm[h] = sm_m[h]; si[h] = 1.f / sm_s[h]; }
    float r[8];
#pragma unroll
    for (int h = 0; h < 8; h++) r[h] = 0.f;
    for (int j = 0; j < cnt; j++) {
        int eid = g_csr_eid[beg + j];
        int s = g_csr_src[beg + j];
        const float* xrow = g_xl1 + s * D1;
#pragma unroll
        for (int h = 0; h < 8; h++) {
            float w = expf(g_logits[eid * 8 + h] - mm[h]) * si[h];
            r[h] += w * xrow[tid + 256 * h];
        }
    }
#pragma unroll
    for (int h = 0; h < 8; h++) {
        int c = tid + 256 * h;
        g_h1[n * D1 + c] = fmaxf(r[h] + b1[c], 0.f);
    }
}

// ---------------- GEMM2: xl2/xr2 = h1 @ {Wl2|Wr2} + bias  -------------------
__global__ __launch_bounds__(256) void k_gemm2(
    const float* __restrict__ Wl2, const float* __restrict__ bl2,
    const float* __restrict__ Wr2, const float* __restrict__ br2)
{
    __shared__ float sA[64 * 33];
    __shared__ __align__(16) float sB[32 * 64];
    int tid = threadIdx.x;
    int r0 = blockIdx.x * 64;
    int ty = tid >> 4, tx = tid & 15;

    u64t acc2[4][2];
#pragma unroll
    for (int i = 0; i < 4; i++)
#pragma unroll
        for (int j = 0; j < 2; j++) acc2[i][j] = 0ull;

    for (int kc = 0; kc < D1; kc += 32) {
        for (int i = tid; i < 512; i += 256) {
            int row = i >> 3;
            int c = (i & 7) << 2;
            float4 v = make_float4(0.f, 0.f, 0.f, 0.f);
            if (r0 + row < Nn) v = *(const float4*)&g_h1[(r0 + row) * D1 + kc + c];
            float* dp = sA + row * 33 + c;
            dp[0] = v.x; dp[1] = v.y; dp[2] = v.z; dp[3] = v.w;
        }
        for (int i = tid; i < 512; i += 256) {
            int kr = i >> 4;
            int c = (i & 15) << 2;
            float4 v;
            if (c < 32) v = *(const float4*)&Wl2[(kc + kr) * D2 + c];
            else        v = *(const float4*)&Wr2[(kc + kr) * D2 + (c - 32)];
            *(float4*)&sB[kr * 64 + c] = v;
        }
        __syncthreads();
#pragma unroll 8
        for (int k = 0; k < 32; k++) {
            const u64t* bp = (const u64t*)&sB[k * 64 + tx * 4];
            u64t b0 = bp[0], b1 = bp[1];
#pragma unroll
            for (int i = 0; i < 4; i++) {
                float a = sA[(ty * 4 + i) * 33 + k];
                u64t a2; PACK2(a2, a);
                FFMA2(acc2[i][0], a2, b0);
                FFMA2(acc2[i][1], a2, b1);
            }
        }
        __syncthreads();
    }
    int c = tx * 4;
    bool left = (c < 32);
    int cc = left ? c : c - 32;
    const float* bias = left ? bl2 : br2;
    float* Cout = left ? g_xl2 : g_xr2;
    float4 bi = *(const float4*)&bias[cc];
#pragma unroll
    for (int i = 0; i < 4; i++) {
        int row = r0 + ty * 4 + i;
        if (row < Nn) {
            float v0, v1, v2, v3;
            UNPACK2(v0, v1, acc2[i][0]);
            UNPACK2(v2, v3, acc2[i][1]);
            float4 o = make_float4(v0 + bi.x, v1 + bi.y, v2 + bi.z, v3 + bi.w);
            *(float4*)&Cout[row * D2 + cc] = o;
        }
    }
}

// ---------------- layer-2 edge logits (warp per edge) -----------------------
__global__ __launch_bounds__(256) void k_elogits2(
    const float* __restrict__ EA, const float* __restrict__ We2,
    const float* __restrict__ att2,
    const int* __restrict__ srcA, const int* __restrict__ dstA)
{
    __shared__ float sW[FIN * D2];
    __shared__ float sAtt[D2];
    int tid = threadIdx.x;
    for (int i = tid; i < FIN * D2; i += 256) sW[i] = We2[i];
    if (tid < D2) sAtt[tid] = att2[tid];
    __syncthreads();

    int wid = tid >> 5, lane = tid & 31;
    int e = blockIdx.x * 8 + wid;
    bool valid = (e < ET);
    int s = 0, d = 0;
    float a0 = 0.f, a1 = 0.f, a2 = 0.f, a3 = 0.f;
    if (valid) {
        if (e < Ee) { s = srcA[e]; d = dstA[e]; }
        else        { s = e - Ee;  d = s; }
        const float* row = (e < Ee) ? (EA + e * FIN) : (g_selfattr + (e - Ee) * FIN);
        a0 = row[lane]; a1 = row[lane + 32]; a2 = row[lane + 64]; a3 = row[lane + 96];
    }
    float acc = 0.f;
#pragma unroll
    for (int kk = 0; kk < 32; kk++)
        acc += __shfl_sync(0xffffffffu, a0, kk) * sW[kk * D2 + lane];
#pragma unroll
    for (int kk = 0; kk < 32; kk++)
        acc += __shfl_sync(0xffffffffu, a1, kk) * sW[(32 + kk) * D2 + lane];
#pragma unroll
    for (int kk = 0; kk < 32; kk++)
        acc += __shfl_sync(0xffffffffu, a2, kk) * sW[(64 + kk) * D2 + lane];
#pragma unroll
    for (int kk = 0; kk < 32; kk++)
        acc += __shfl_sync(0xffffffffu, a3, kk) * sW[(96 + kk) * D2 + lane];

    float u = acc;
    if (valid) u += g_xl2[s * D2 + lane] + g_xr2[d * D2 + lane];
    u = u > 0.f ? u : NEG * u;
    float p = u * sAtt[lane];
    p += __shfl_xor_sync(0xffffffffu, p, 16);
    p += __shfl_xor_sync(0xffffffffu, p, 8);
    p += __shfl_xor_sync(0xffffffffu, p, 4);
    p += __shfl_xor_sync(0xffffffffu, p, 2);
    p += __shfl_xor_sync(0xffffffffu, p, 1);
    if (valid && lane == 0) g_logits2[e] = p;
}

// ---------------- layer-2 softmax + aggregation + ReLU (warp per node) ------
__global__ __launch_bounds__(256) void k_agg2(const float* __restrict__ b2,
                                              float* __restrict__ out)
{
    int gid = blockIdx.x * 256 + threadIdx.x;
    int n = gid >> 5;
    int lane = gid & 31;
    if (n >= Nn) return;
    int beg = g_off[n];
    int cnt = g_deg[n] + 1;
    float m = -1e30f;
    for (int j = 0; j < cnt; j++)
        m = fmaxf(m, g_logits2[g_csr_eid[beg + j]]);
    float sden = 0.f;
    for (int j = 0; j < cnt; j++)
        sden += expf(g_logits2[g_csr_eid[beg + j]] - m);
    float inv = 1.f / sden;
    float o = 0.f;
    for (int j = 0; j < cnt; j++) {
        int eid = g_csr_eid[beg + j];
        int sn = g_csr_src[beg + j];
        float w = expf(g_logits2[eid] - m) * inv;
        o += w * g_xl2[sn * D2 + lane];
    }
    out[n * D2 + lane] = fmaxf(o + b2[lane], 0.f);
}

// ---------------- launch -----------------------------------------------------
extern "C" void kernel_launch(void* const* d_in, const int* in_sizes, int n_in,
                              void* d_out, int out_size)
{
    const float* x    = (const float*)d_in[0];
    const int*   ei   = (const int*)  d_in[1];
    const float* ea   = (const float*)d_in[2];
    const float* Wl1  = (const float*)d_in[3];
    const float* bl1  = (const float*)d_in[4];
    const float* Wr1  = (const float*)d_in[5];
    const float* br1  = (const float*)d_in[6];
    const float* We1  = (const float*)d_in[7];
    const float* att1 = (const float*)d_in[8];
    const float* b1   = (const float*)d_in[9];
    const float* Wl2  = (const float*)d_in[10];
    const float* bl2  = (const float*)d_in[11];
    const float* Wr2  = (const float*)d_in[12];
    const float* br2  = (const float*)d_in[13];
    const float* We2  = (const float*)d_in[14];
    const float* att2 = (const float*)d_in[15];
    const float* b2   = (const float*)d_in[16];
    float* out = (float*)d_out;

    const int* srcA = ei;
    const int* dstA = ei + Ee;

    const size_t SM_EL1 = (size_t)(128 * 129 + 128 * 64 + 128 * 8) * sizeof(float)
                        + 256 * sizeof(int);
    cudaFuncSetAttribute(k_elogits1, cudaFuncAttributeMaxDynamicSharedMemorySize,
                         (int)SM_EL1);

    k_init <<<(Nn + 255) / 256, 256>>>();
    k_count<<<(Ee + 255) / 256, 256>>>(dstA);
    k_scan <<<1, 1024>>>();
    k_fill <<<(Ee + Nn + 255) / 256, 256>>>(srcA, dstA);
    k_selfattr<<<Nn, 128>>>(ea);

    dim3 g1(D1 / 64, (Nn + 63) / 64);
    k_gemm1<<<g1, 256>>>(x, Wl1, bl1, 0);
    k_gemm1<<<g1, 256>>>(x, Wr1, br1, 1);

    k_elogits1<<<(ET + 127) / 128, 256, SM_EL1>>>(ea, We1, att1, srcA, dstA);
    k_agg1<<<Nn, 256>>>(b1);

    k_gemm2<<<(Nn + 63) / 64, 256>>>(Wl2, bl2, Wr2, br2);
    k_elogits2<<<(ET + 7) / 8, 256>>>(ea, We2, att2, srcA, dstA);
    k_agg2<<<(Nn * 32 + 255) / 256, 256>>>(b2, out);

    (void)in_sizes; (void)n_in; (void)out_size;
}